// round 6
// baseline (speedup 1.0000x reference)
#include <cuda_runtime.h>
#include <math.h>

#define BATCH 4
#define SEQ   2048
#define EMB   512
#define NH    8
#define HD    64
#define MROWS (BATCH*SEQ)   // 8192
#define FULLW 0xffffffffu

// Scratch (device globals: allocation-free per harness rules)
__device__ float g_Q[BATCH*NH*SEQ*HD];   // (b,h,n,d)
__device__ float g_K[BATCH*NH*SEQ*HD];
__device__ float g_V[BATCH*NH*SEQ*HD];
__device__ float g_AO[BATCH*SEQ*EMB];    // (b,n,e)

// ---------------------------------------------------------------------------
__device__ __forceinline__ unsigned f2tf(float f) {
    unsigned u; asm("cvt.rna.tf32.f32 %0, %1;" : "=r"(u) : "f"(f)); return u;
}
__device__ __forceinline__ float tfbits(float f) {
    return __uint_as_float(f2tf(f));
}
__device__ __forceinline__ void mma8(float* c, const unsigned* a, const unsigned* b) {
    asm volatile(
        "mma.sync.aligned.m16n8k8.row.col.f32.tf32.tf32.f32 "
        "{%0,%1,%2,%3}, {%4,%5,%6,%7}, {%8,%9}, {%0,%1,%2,%3};"
        : "+f"(c[0]), "+f"(c[1]), "+f"(c[2]), "+f"(c[3])
        : "r"(a[0]), "r"(a[1]), "r"(a[2]), "r"(a[3]), "r"(b[0]), "r"(b[1]));
}
#define U(x) __float_as_uint(x)

// Quad butterfly transpose: within a quad (lanes c4=0..3 share r4), input
// p0 = col 2c4, p1 = col 2c4+1 of an 8-col group; output alo = col c4,
// ahi = col c4+4. 2 shfl.bfly + selects.
__device__ __forceinline__ void quad_tr(unsigned p0, unsigned p1, int c4,
                                        unsigned& alo, unsigned& ahi) {
    unsigned keep  = (c4 & 1) ? p1 : p0;
    unsigned sent0 = (c4 & 1) ? p0 : p1;
    unsigned got0  = __shfl_xor_sync(FULLW, sent0, 1);
    unsigned sent1 = ((c4 ^ (c4 >> 1)) & 1) ? keep : got0;
    unsigned got1  = __shfl_xor_sync(FULLW, sent1, 2);
    alo = (c4 == 0) ? keep : ((c4 == 1) ? got0 : got1);
    ahi = (c4 == 3) ? keep : ((c4 == 2) ? got0 : got1);
}

// Fragment-native smem layout: tile X[kc][row][16]; logical col c16 of chunk kc
// stored at pos = ((c16&3) ^ ((row>>2)&3) ^ kc)*4 + (c16>>2).
// LDS.128 at quad q = (c4 ^ (row>>2) ^ kc)&3 yields cols {c4,c4+4,c4+8,c4+12}.

// ---------------------------------------------------------------------------
// GEMM core: C[m,e] = sum_k A[m,k] * W[e,k]. CTA 128x64, BK=32, 256 threads,
// 8 warps (4 m x 2 n), warp tile 32x32. Double-buffered smem, 1 sync/iter.
// smem: 2 stages x (A 128x32 + W 64x32) = 12288 floats = 48KB.
// ---------------------------------------------------------------------------
__device__ __forceinline__ void gemm_core_db(const float* __restrict__ Ap,
                                             const float* __restrict__ W,
                                             float* sm, int m0, int e0,
                                             float acc[2][4][4])
{
    const int tid  = threadIdx.x;
    const int lane = tid & 31;
    const int wid  = tid >> 5;
    const int r4 = lane >> 2, c4 = lane & 3;
    const int wy = wid >> 1, wx = wid & 1;
    const int rk4 = (r4 >> 2) & 3;          // 0/1

    const int rowA = tid >> 1;              // 0..127
    const int kcA  = tid & 1;               // chunk within BK=32
    const int rowB = tid >> 2;              // 0..63
    const int kcB  = (tid & 3) >> 1;
    const int uB   = (tid & 1) * 2;         // float4 slot base for B

    const float* aP = Ap + (size_t)(m0 + rowA) * EMB + kcA * 16;
    const float* wP = W  + (size_t)(e0 + rowB) * EMB + kcB * 16 + (tid & 1) * 8;

    const int rxA = ((rowA >> 2) ^ kcA) & 3;
    const int rxB = ((rowB >> 2) ^ kcB) & 3;
    const int eB0 = ((0 ^ rxB) & 3) << 2, eB1 = ((1 ^ rxB) & 3) << 2;
    const int eB2 = ((2 ^ rxB) & 3) << 2, eB3 = ((3 ^ rxB) & 3) << 2;
    const int eA0 = ((0 ^ rxA) & 3) << 2, eA1 = ((1 ^ rxA) & 3) << 2;
    const int eA2 = ((2 ^ rxA) & 3) << 2, eA3 = ((3 ^ rxA) & 3) << 2;

    float* adB = sm + kcA * 2048 + rowA * 16;
    float* wdB = sm + 4096 + kcB * 1024 + rowB * 16;

    float4 ar0 = ((const float4*)aP)[0], ar1 = ((const float4*)aP)[1];
    float4 ar2 = ((const float4*)aP)[2], ar3 = ((const float4*)aP)[3];
    float4 wr0 = ((const float4*)wP)[0], wr1 = ((const float4*)wP)[1];

    for (int it = 0; it < 16; ++it) {
        const int soff = (it & 1) * 6144;
        float* ad = adB + soff;
        ad[eA0    ] = tfbits(ar0.x); ad[eA1    ] = tfbits(ar0.y);
        ad[eA2    ] = tfbits(ar0.z); ad[eA3    ] = tfbits(ar0.w);
        ad[eA0 + 1] = tfbits(ar1.x); ad[eA1 + 1] = tfbits(ar1.y);
        ad[eA2 + 1] = tfbits(ar1.z); ad[eA3 + 1] = tfbits(ar1.w);
        ad[eA0 + 2] = tfbits(ar2.x); ad[eA1 + 2] = tfbits(ar2.y);
        ad[eA2 + 2] = tfbits(ar2.z); ad[eA3 + 2] = tfbits(ar2.w);
        ad[eA0 + 3] = tfbits(ar3.x); ad[eA1 + 3] = tfbits(ar3.y);
        ad[eA2 + 3] = tfbits(ar3.z); ad[eA3 + 3] = tfbits(ar3.w);
        float* wd = wdB + soff;
        wd[eB0 + uB    ] = tfbits(wr0.x); wd[eB1 + uB    ] = tfbits(wr0.y);
        wd[eB2 + uB    ] = tfbits(wr0.z); wd[eB3 + uB    ] = tfbits(wr0.w);
        wd[eB0 + uB + 1] = tfbits(wr1.x); wd[eB1 + uB + 1] = tfbits(wr1.y);
        wd[eB2 + uB + 1] = tfbits(wr1.z); wd[eB3 + uB + 1] = tfbits(wr1.w);
        __syncthreads();

        if (it < 15) {                       // prefetch next BK=32 chunk
            const float* a2 = aP + (it + 1) * 32;
            const float* w2 = wP + (it + 1) * 32;
            ar0 = ((const float4*)a2)[0]; ar1 = ((const float4*)a2)[1];
            ar2 = ((const float4*)a2)[2]; ar3 = ((const float4*)a2)[3];
            wr0 = ((const float4*)w2)[0]; wr1 = ((const float4*)w2)[1];
        }

        #pragma unroll
        for (int kc = 0; kc < 2; ++kc) {
            const float* As_ = sm + soff + kc * 2048;
            const float* Ws_ = sm + soff + 4096 + kc * 1024;
            float4 alo[2], ahi[2], bv[4];
            #pragma unroll
            for (int mi = 0; mi < 2; ++mi) {
                int row = wy * 32 + mi * 16 + r4;
                int q1 = (c4 ^ rk4 ^ kc) & 3;
                alo[mi] = *(const float4*)&As_[row * 16 + (q1 << 2)];
                ahi[mi] = *(const float4*)&As_[(row + 8) * 16 + ((q1 ^ 2) << 2)];
            }
            #pragma unroll
            for (int ni = 0; ni < 4; ++ni) {
                int n = wx * 32 + ni * 8 + r4;
                int qb = (c4 ^ ((2 * ni + rk4) ^ kc)) & 3;
                bv[ni] = *(const float4*)&Ws_[n * 16 + (qb << 2)];
            }
            #pragma unroll
            for (int mi = 0; mi < 2; ++mi) {
                unsigned a0v[4] = {U(alo[mi].x), U(ahi[mi].x), U(alo[mi].y), U(ahi[mi].y)};
                unsigned a1v[4] = {U(alo[mi].z), U(ahi[mi].z), U(alo[mi].w), U(ahi[mi].w)};
                #pragma unroll
                for (int ni = 0; ni < 4; ++ni) {
                    unsigned b0v[2] = {U(bv[ni].x), U(bv[ni].y)};
                    unsigned b1v[2] = {U(bv[ni].z), U(bv[ni].w)};
                    mma8(acc[mi][ni], a0v, b0v);
                    mma8(acc[mi][ni], a1v, b1v);
                }
            }
        }
    }
}

__global__ __launch_bounds__(256, 2) void gemm_qkv(const float* __restrict__ x,
                                                   const float* __restrict__ WQ,
                                                   const float* __restrict__ WK,
                                                   const float* __restrict__ WV)
{
    __shared__ float sm[12288];
    const int z = blockIdx.z;
    const float* W = (z == 0) ? WQ : ((z == 1) ? WK : WV);
    float* dst = (z == 0) ? g_Q : ((z == 1) ? g_K : g_V);
    const int m0 = blockIdx.y * 128, e0 = blockIdx.x * 64;
    float acc[2][4][4] = {};
    gemm_core_db(x, W, sm, m0, e0, acc);

    const int tid = threadIdx.x, lane = tid & 31, wid = tid >> 5;
    const int wy = wid >> 1, wx = wid & 1, r4 = lane >> 2, c4 = lane & 3;
    const int h = blockIdx.x;               // 64-wide e-tile == one head
    #pragma unroll
    for (int mi = 0; mi < 2; ++mi) {
        #pragma unroll
        for (int ni = 0; ni < 4; ++ni) {
            int mlo = m0 + wy * 32 + mi * 16 + r4;
            int d   = wx * 32 + ni * 8 + c4 * 2;
            int b0 = mlo >> 11, n0 = mlo & (SEQ - 1);
            *(float2*)&dst[((size_t)(b0 * NH + h) * SEQ + n0) * HD + d] =
                make_float2(acc[mi][ni][0], acc[mi][ni][1]);
            int m2 = mlo + 8;
            int b1 = m2 >> 11, n1 = m2 & (SEQ - 1);
            *(float2*)&dst[((size_t)(b1 * NH + h) * SEQ + n1) * HD + d] =
                make_float2(acc[mi][ni][2], acc[mi][ni][3]);
        }
    }
}

__global__ __launch_bounds__(256, 2) void gemm_out(const float* __restrict__ WO,
                                                   float* __restrict__ dout)
{
    __shared__ float sm[12288];
    const int m0 = blockIdx.y * 128, e0 = blockIdx.x * 64;
    float acc[2][4][4] = {};
    gemm_core_db(g_AO, WO, sm, m0, e0, acc);

    const int tid = threadIdx.x, lane = tid & 31, wid = tid >> 5;
    const int wy = wid >> 1, wx = wid & 1, r4 = lane >> 2, c4 = lane & 3;
    #pragma unroll
    for (int mi = 0; mi < 2; ++mi) {
        #pragma unroll
        for (int ni = 0; ni < 4; ++ni) {
            int mlo = m0 + wy * 32 + mi * 16 + r4;
            int e   = e0 + wx * 32 + ni * 8 + c4 * 2;
            *(float2*)&dout[(size_t)mlo * EMB + e] =
                make_float2(acc[mi][ni][0], acc[mi][ni][1]);
            *(float2*)&dout[(size_t)(mlo + 8) * EMB + e] =
                make_float2(acc[mi][ni][2], acc[mi][ni][3]);
        }
    }
}

// ---------------------------------------------------------------------------
// Causal flash attention: tf32 mma, fragment-native smem, double-buffered K/V,
// register-shuffle P transpose (no P smem). CTA = (b,h) x 128 q-rows, 8 warps,
// 2 CTAs/SM. Smem: Qs 32KB + Ks 2x16KB + Vt 2x16KB = 96KB.
// ---------------------------------------------------------------------------
__global__ __launch_bounds__(256, 2) void attn_tc()
{
    extern __shared__ float smx[];
    float* Qs = smx;                        // [4][128][16] = 8192

    const int bh = blockIdx.x;
    const int qt = (int)(gridDim.y - 1 - blockIdx.y);   // largest tiles first
    const int q0 = qt * 128;
    const int tid  = threadIdx.x;
    const int lane = tid & 31;
    const int wid  = tid >> 5;
    const int r4 = lane >> 2, c4 = lane & 3;
    const int rk4 = (r4 >> 2) & 3;          // 0/1

    const float* Qg = g_Q + (size_t)bh * SEQ * HD;
    const float* Kg = g_K + (size_t)bh * SEQ * HD;
    const float* Vg = g_V + (size_t)bh * SEQ * HD;

    // Q -> fragment-native smem, prescaled by 0.125
    #pragma unroll
    for (int i = 0; i < 8; i++) {
        int idx = tid + i * 256;
        int r = idx >> 4, d4 = (idx & 15) * 4;
        float4 v = *(const float4*)&Qg[(size_t)(q0 + r) * HD + d4];
        int kc = d4 >> 4, t = (d4 & 15) >> 2;
        int rk = ((r >> 2) ^ kc) & 3;
        float* qd = &Qs[(kc * 128 + r) * 16 + t];
        qd[((0^rk)&3) << 2] = tfbits(v.x * 0.125f);
        qd[((1^rk)&3) << 2] = tfbits(v.y * 0.125f);
        qd[((2^rk)&3) << 2] = tfbits(v.z * 0.125f);
        qd[((3^rk)&3) << 2] = tfbits(v.w * 0.125f);
    }

    float m0r = -1e30f, m1r = -1e30f, l0r = 0.0f, l1r = 0.0f;
    float o[8][4] = {};

    const int ktiles = (q0 >> 6) + 2;
    const int maskStart = ktiles - 2;

    // prologue: load KV tile 0 into registers
    float4 kr[4], vr[4];
    #pragma unroll
    for (int i = 0; i < 4; i++) {
        int idx = tid + i * 256;
        int c = idx >> 4, d4 = (idx & 15) * 4;
        kr[i] = *(const float4*)&Kg[(size_t)c * HD + d4];
        vr[i] = *(const float4*)&Vg[(size_t)c * HD + d4];
    }

    for (int kt = 0; kt < ktiles; kt++) {
        float* Ksb = smx + 8192  + (kt & 1) * 4096;   // [4][64][16]
        float* Vtb = smx + 16384 + (kt & 1) * 4096;   // [4][64][16] (transposed)

        // store staged registers -> smem (cvt + swizzle)
        #pragma unroll
        for (int i = 0; i < 4; i++) {
            int idx = tid + i * 256;
            int c = idx >> 4, d4 = (idx & 15) * 4;
            int kc = d4 >> 4, t = (d4 & 15) >> 2;
            int rkK = ((c >> 2) ^ kc) & 3;
            float* kd = &Ksb[(kc * 64 + c) * 16 + t];
            kd[((0^rkK)&3) << 2] = tfbits(kr[i].x);
            kd[((1^rkK)&3) << 2] = tfbits(kr[i].y);
            kd[((2^rkK)&3) << 2] = tfbits(kr[i].z);
            kd[((3^rkK)&3) << 2] = tfbits(kr[i].w);
            int kcv = c >> 4, tv = (c & 15) >> 2;
            int qv = ((c & 3) ^ ((d4 >> 2) & 3) ^ kcv) & 3;
            float* vd = &Vtb[(kcv * 64 + d4) * 16 + (qv << 2) + tv];
            vd[0]  = tfbits(vr[i].x);
            vd[16] = tfbits(vr[i].y);
            vd[32] = tfbits(vr[i].z);
            vd[48] = tfbits(vr[i].w);
        }
        __syncthreads();

        // prefetch next K tile (overlaps QK compute)
        if (kt + 1 < ktiles) {
            const float* Kn = Kg + (size_t)(kt + 1) * 64 * HD;
            #pragma unroll
            for (int i = 0; i < 4; i++) {
                int idx = tid + i * 256;
                kr[i] = *(const float4*)&Kn[(size_t)(idx >> 4) * HD + (idx & 15) * 4];
            }
        }

        // S = Q K^T (warp: 16 x 64)
        float s[8][4] = {};
        #pragma unroll
        for (int kc = 0; kc < 4; kc++) {
            int qr = kc * 128 + wid * 16 + r4;
            int q1 = (c4 ^ rk4 ^ kc) & 3;
            float4 qlo = *(const float4*)&Qs[qr * 16 + (q1 << 2)];
            float4 qhi = *(const float4*)&Qs[(qr + 8) * 16 + ((q1 ^ 2) << 2)];
            unsigned a0v[4] = {U(qlo.x), U(qhi.x), U(qlo.y), U(qhi.y)};
            unsigned a1v[4] = {U(qlo.z), U(qhi.z), U(qlo.w), U(qhi.w)};
            #pragma unroll
            for (int ni = 0; ni < 8; ni++) {
                int n = ni * 8 + r4;
                int qb = (c4 ^ ((2 * ni + rk4) ^ kc)) & 3;
                float4 bv = *(const float4*)&Ksb[(kc * 64 + n) * 16 + (qb << 2)];
                unsigned b0v[2] = {U(bv.x), U(bv.y)};
                unsigned b1v[2] = {U(bv.z), U(bv.w)};
                mma8(s[ni], a0v, b0v);
                mma8(s[ni], a1v, b1v);
            }
        }

        // prefetch next V tile (overlaps softmax + PV)
        if (kt + 1 < ktiles) {
            const float* Vn = Vg + (size_t)(kt + 1) * 64 * HD;
            #pragma unroll
            for (int i = 0; i < 4; i++) {
                int idx = tid + i * 256;
                vr[i] = *(const float4*)&Vn[(size_t)(idx >> 4) * HD + (idx & 15) * 4];
            }
        }

        // causal mask (last two ktiles only)
        if (kt >= maskStart) {
            int k0 = kt * 64;
            int grow = q0 + wid * 16 + r4;
            #pragma unroll
            for (int ni = 0; ni < 8; ni++) {
                int gcol = k0 + ni * 8 + c4 * 2;
                if (gcol     > grow    ) s[ni][0] = -1e30f;
                if (gcol + 1 > grow    ) s[ni][1] = -1e30f;
                if (gcol     > grow + 8) s[ni][2] = -1e30f;
                if (gcol + 1 > grow + 8) s[ni][3] = -1e30f;
            }
        }

        // online softmax (2 rows/thread, quad reduce)
        float mx0 = -1e30f, mx1 = -1e30f;
        #pragma unroll
        for (int ni = 0; ni < 8; ni++) {
            mx0 = fmaxf(mx0, fmaxf(s[ni][0], s[ni][1]));
            mx1 = fmaxf(mx1, fmaxf(s[ni][2], s[ni][3]));
        }
        mx0 = fmaxf(mx0, __shfl_xor_sync(FULLW, mx0, 1));
        mx0 = fmaxf(mx0, __shfl_xor_sync(FULLW, mx0, 2));
        mx1 = fmaxf(mx1, __shfl_xor_sync(FULLW, mx1, 1));
        mx1 = fmaxf(mx1, __shfl_xor_sync(FULLW, mx1, 2));
        float mn0 = fmaxf(m0r, mx0), mn1 = fmaxf(m1r, mx1);
        float al0 = __expf(m0r - mn0), al1 = __expf(m1r - mn1);
        float ls0 = 0.0f, ls1 = 0.0f;
        #pragma unroll
        for (int ni = 0; ni < 8; ni++) {
            s[ni][0] = __expf(s[ni][0] - mn0);
            s[ni][1] = __expf(s[ni][1] - mn0);
            s[ni][2] = __expf(s[ni][2] - mn1);
            s[ni][3] = __expf(s[ni][3] - mn1);
            ls0 += s[ni][0] + s[ni][1];
            ls1 += s[ni][2] + s[ni][3];
        }
        ls0 += __shfl_xor_sync(FULLW, ls0, 1);
        ls0 += __shfl_xor_sync(FULLW, ls0, 2);
        ls1 += __shfl_xor_sync(FULLW, ls1, 1);
        ls1 += __shfl_xor_sync(FULLW, ls1, 2);
        l0r = l0r * al0 + ls0;  m0r = mn0;
        l1r = l1r * al1 + ls1;  m1r = mn1;

        #pragma unroll
        for (int ni = 0; ni < 8; ni++) {
            o[ni][0] *= al0; o[ni][1] *= al0;
            o[ni][2] *= al1; o[ni][3] *= al1;
        }

        // O += P @ V ; A-fragments built in-register via quad transpose
        #pragma unroll
        for (int kcv = 0; kcv < 4; kcv++) {
            float4 bvv[8];
            #pragma unroll
            for (int di = 0; di < 8; di++) {
                int n = di * 8 + r4;
                int qb = (c4 ^ ((2 * di + rk4) ^ kcv)) & 3;
                bvv[di] = *(const float4*)&Vtb[(kcv * 64 + n) * 16 + (qb << 2)];
            }
            #pragma unroll
            for (int sub = 0; sub < 2; sub++) {
                int ni = 2 * kcv + sub;
                unsigned aL0, aH0, aL1, aH1;
                quad_tr(f2tf(s[ni][0]), f2tf(s[ni][1]), c4, aL0, aH0);
                quad_tr(f2tf(s[ni][2]), f2tf(s[ni][3]), c4, aL1, aH1);
                unsigned a[4] = {aL0, aL1, aH0, aH1};
                #pragma unroll
                for (int di = 0; di < 8; di++) {
                    unsigned b[2];
                    if (sub) { b[0] = U(bvv[di].z); b[1] = U(bvv[di].w); }
                    else     { b[0] = U(bvv[di].x); b[1] = U(bvv[di].y); }
                    mma8(o[di], a, b);
                }
            }
        }
    }

    // epilogue: normalize, write to g_AO (b, n, h*64+d)
    float inv0 = 1.0f / l0r, inv1 = 1.0f / l1r;
    const int b = bh >> 3, h = bh & 7;
    const int row0 = q0 + wid * 16 + r4;
    #pragma unroll
    for (int ni = 0; ni < 8; ni++) {
        int e = h * 64 + ni * 8 + c4 * 2;
        *(float2*)&g_AO[(size_t)(b * SEQ + row0    ) * EMB + e] =
            make_float2(o[ni][0] * inv0, o[ni][1] * inv0);
        *(float2*)&g_AO[(size_t)(b * SEQ + row0 + 8) * EMB + e] =
            make_float2(o[ni][2] * inv1, o[ni][3] * inv1);
    }
}

// ---------------------------------------------------------------------------

extern "C" void kernel_launch(void* const* d_in, const int* in_sizes, int n_in,
                              void* d_out, int out_size)
{
    const float* x  = (const float*)d_in[0];
    const float* WQ = (const float*)d_in[1];
    const float* WK = (const float*)d_in[2];
    const float* WV = (const float*)d_in[3];
    const float* WO = (const float*)d_in[4];
    // d_in[5] = mask (tril) — causal, applied analytically in-kernel.
    float* out = (float*)d_out;

    const int SMEM_ATTN = 24576 * (int)sizeof(float);   // 96KB
    static bool attr_set = false;
    if (!attr_set) {
        cudaFuncSetAttribute(attn_tc,
                             cudaFuncAttributeMaxDynamicSharedMemorySize, SMEM_ATTN);
        attr_set = true;
    }

    gemm_qkv<<<dim3(EMB / 64, MROWS / 128, 3), 256>>>(x, WQ, WK, WV);

    attn_tc<<<dim3(BATCH * NH, SEQ / 128), 256, SMEM_ATTN>>>();

    gemm_out<<<dim3(EMB / 64, MROWS / 128), 256>>>(WO, out);
}

// round 7
// speedup vs baseline: 1.2705x; 1.2705x over previous
#include <cuda_runtime.h>
#include <math.h>

#define BATCH 4
#define SEQ   2048
#define EMB   512
#define NH    8
#define HD    64
#define MROWS (BATCH*SEQ)   // 8192

// Scratch (device globals: allocation-free per harness rules)
__device__ float g_Q[BATCH*NH*SEQ*HD];   // (b,h,n,d)
__device__ float g_K[BATCH*NH*SEQ*HD];
__device__ float g_V[BATCH*NH*SEQ*HD];
__device__ float g_AO[BATCH*SEQ*EMB];    // (b,n,e)

// ---------------------------------------------------------------------------
// tf32 helpers
// ---------------------------------------------------------------------------
__device__ __forceinline__ unsigned f2tf(float f) {
    unsigned u; asm("cvt.rna.tf32.f32 %0, %1;" : "=r"(u) : "f"(f)); return u;
}
__device__ __forceinline__ float tfbits(float f) {
    return __uint_as_float(f2tf(f));
}
__device__ __forceinline__ void mma8(float* c, const unsigned* a, const unsigned* b) {
    asm volatile(
        "mma.sync.aligned.m16n8k8.row.col.f32.tf32.tf32.f32 "
        "{%0,%1,%2,%3}, {%4,%5,%6,%7}, {%8,%9}, {%0,%1,%2,%3};"
        : "+f"(c[0]), "+f"(c[1]), "+f"(c[2]), "+f"(c[3])
        : "r"(a[0]), "r"(a[1]), "r"(a[2]), "r"(a[3]), "r"(b[0]), "r"(b[1]));
}
#define U(x) __float_as_uint(x)

// Fragment-native smem layout:
//   tile X[row][16] per k16 chunk; logical col c16 stored at
//   pos = ((c16&3) ^ ((row>>2)&3))*4 + (c16>>2)
// LDS.128 at quad q = (c4 ^ (row>>2))&3 yields cols {c4,c4+4,c4+8,c4+12}.

// ---------------------------------------------------------------------------
// GEMM core (512 threads): C[m,e] = sum_k A[m,k] * W[e,k].
// CTA tile 128x128, BK=16, 16 warps in 4x4 grid, warp tile 32x32.
// DOUBLE-BUFFERED smem (2 x 16KB), ONE __syncthreads per k16 iteration,
// next-chunk LDG prefetch overlapping compute. Otherwise identical to R4.
// ---------------------------------------------------------------------------
__device__ __forceinline__ void gemm_core512(const float* __restrict__ Ap,
                                             const float* __restrict__ W,
                                             float* sm,      // [2][4096]
                                             int m0, int e0,
                                             float acc[2][4][4])
{
    const int tid  = threadIdx.x;
    const int lane = tid & 31;
    const int r4 = lane >> 2, c4 = lane & 3;
    const int wid = tid >> 5;
    const int wy = wid >> 2, wx = wid & 3;
    const int rkA  = (r4 >> 2) & 3;      // 0 or 1

    const int rowL = tid >> 2;           // 0..127
    const int kOff = (tid & 3) * 4;      // 0,4,8,12
    const int tS   = kOff >> 2;          // 0..3
    const int rkst = (rowL >> 2) & 3;

    const float* aP = &Ap[(size_t)(m0 + rowL) * EMB + kOff];
    const float* wP = &W [(size_t)(e0 + rowL) * EMB + kOff];

    float4 a0 = *(const float4*)aP;
    float4 w0 = *(const float4*)wP;

    const int e0i = ((0 ^ rkst) & 3) << 2, e1i = ((1 ^ rkst) & 3) << 2;
    const int e2i = ((2 ^ rkst) & 3) << 2, e3i = ((3 ^ rkst) & 3) << 2;

    #pragma unroll 4
    for (int it = 0; it < 32; ++it) {    // k0 = it*16
        float* stg = sm + (it & 1) * 4096;
        {
            float* ad = stg + (rowL << 4) + tS;
            ad[e0i] = tfbits(a0.x);
            ad[e1i] = tfbits(a0.y);
            ad[e2i] = tfbits(a0.z);
            ad[e3i] = tfbits(a0.w);
            float* wd = stg + 2048 + (rowL << 4) + tS;
            wd[e0i] = tfbits(w0.x);
            wd[e1i] = tfbits(w0.y);
            wd[e2i] = tfbits(w0.z);
            wd[e3i] = tfbits(w0.w);
        }
        __syncthreads();                 // single barrier per iteration

        // prefetch next chunk (overlaps with compute below)
        if (it < 31) {
            a0 = *(const float4*)(aP + (it + 1) * 16);
            w0 = *(const float4*)(wP + (it + 1) * 16);
        }

        const float* As_ = stg;
        const float* Ws_ = stg + 2048;
        float4 alo[2], ahi[2], bv[4];
        #pragma unroll
        for (int mi = 0; mi < 2; mi++) {
            int r = wy * 32 + mi * 16 + r4;
            alo[mi] = *(const float4*)&As_[(r << 4)       + (((c4 ^ rkA)     & 3) << 2)];
            ahi[mi] = *(const float4*)&As_[((r + 8) << 4) + (((c4 ^ rkA ^ 2) & 3) << 2)];
        }
        #pragma unroll
        for (int ni = 0; ni < 4; ni++) {
            int n = wx * 32 + ni * 8 + r4;
            int rkB = (2 * ni + rkA) & 3;
            bv[ni] = *(const float4*)&Ws_[(n << 4) + (((c4 ^ rkB) & 3) << 2)];
        }
        #pragma unroll
        for (int mi = 0; mi < 2; mi++) {
            unsigned a0v[4] = {U(alo[mi].x), U(ahi[mi].x), U(alo[mi].y), U(ahi[mi].y)};
            unsigned a1v[4] = {U(alo[mi].z), U(ahi[mi].z), U(alo[mi].w), U(ahi[mi].w)};
            #pragma unroll
            for (int ni = 0; ni < 4; ni++) {
                unsigned b0v[2] = {U(bv[ni].x), U(bv[ni].y)};
                unsigned b1v[2] = {U(bv[ni].z), U(bv[ni].w)};
                mma8(acc[mi][ni], a0v, b0v);
                mma8(acc[mi][ni], a1v, b1v);
            }
        }
    }
}

// QKV fused projection: z selects WQ/WK/WV, scatter to (b,h,n,d)
__global__ __launch_bounds__(512) void gemm_qkv(const float* __restrict__ x,
                                                const float* __restrict__ WQ,
                                                const float* __restrict__ WK,
                                                const float* __restrict__ WV)
{
    __shared__ float sm[8192];           // 2 stages x (As 2048 + Ws 2048)
    const int z = blockIdx.z;
    const float* W = (z == 0) ? WQ : ((z == 1) ? WK : WV);
    float* dst = (z == 0) ? g_Q : ((z == 1) ? g_K : g_V);

    const int m0 = blockIdx.y * 128;
    const int e0 = blockIdx.x * 128;
    float acc[2][4][4] = {};
    gemm_core512(x, W, sm, m0, e0, acc);

    const int tid = threadIdx.x, lane = tid & 31, wid = tid >> 5;
    const int wy = wid >> 2, wx = wid & 3, r4 = lane >> 2, c4 = lane & 3;
    #pragma unroll
    for (int mi = 0; mi < 2; mi++) {
        #pragma unroll
        for (int ni = 0; ni < 4; ni++) {
            int mlo = m0 + wy * 32 + mi * 16 + r4;
            int e   = e0 + wx * 32 + ni * 8 + c4 * 2;
            int h = e >> 6, d = e & 63;
            int b0 = mlo >> 11, n0 = mlo & (SEQ - 1);
            *(float2*)&dst[((size_t)(b0 * NH + h) * SEQ + n0) * HD + d] =
                make_float2(acc[mi][ni][0], acc[mi][ni][1]);
            int m2 = mlo + 8;
            int b1 = m2 >> 11, n1 = m2 & (SEQ - 1);
            *(float2*)&dst[((size_t)(b1 * NH + h) * SEQ + n1) * HD + d] =
                make_float2(acc[mi][ni][2], acc[mi][ni][3]);
        }
    }
}

// Output projection: A = g_AO, row-major output
__global__ __launch_bounds__(512) void gemm_out(const float* __restrict__ WO,
                                                float* __restrict__ dout)
{
    __shared__ float sm[8192];
    const int m0 = blockIdx.y * 128;
    const int e0 = blockIdx.x * 128;
    float acc[2][4][4] = {};
    gemm_core512(g_AO, WO, sm, m0, e0, acc);

    const int tid = threadIdx.x, lane = tid & 31, wid = tid >> 5;
    const int wy = wid >> 2, wx = wid & 3, r4 = lane >> 2, c4 = lane & 3;
    #pragma unroll
    for (int mi = 0; mi < 2; mi++) {
        #pragma unroll
        for (int ni = 0; ni < 4; ni++) {
            int mlo = m0 + wy * 32 + mi * 16 + r4;
            int e   = e0 + wx * 32 + ni * 8 + c4 * 2;
            *(float2*)&dout[(size_t)mlo * EMB + e] =
                make_float2(acc[mi][ni][0], acc[mi][ni][1]);
            *(float2*)&dout[(size_t)(mlo + 8) * EMB + e] =
                make_float2(acc[mi][ni][2], acc[mi][ni][3]);
        }
    }
}

// ---------------------------------------------------------------------------
// Causal flash attention — VERBATIM the R3/R4 version (part of the 390us best).
// CTA = (b,h) x 128 q-rows. 8 warps x 16 rows. 2 CTAs/SM.
// ---------------------------------------------------------------------------
__global__ __launch_bounds__(256, 2) void attn_tc()
{
    extern __shared__ float smx[];
    float* Qs = smx;                 // 8192
    float* Ks = smx + 8192;          // 4096
    float* Vt = smx + 12288;         // 4096
    float* Ps = smx + 16384;         // 8192

    const int bh = blockIdx.x;                      // 0..31
    const int qt = (int)(gridDim.y - 1 - blockIdx.y); // largest tiles first
    const int q0 = qt * 128;
    const int tid  = threadIdx.x;
    const int lane = tid & 31;
    const int wid  = tid >> 5;
    const int r4 = lane >> 2;
    const int c4 = lane & 3;
    const int rk4 = (r4 >> 2) & 3;   // 0 or 1

    const float* Qg = g_Q + (size_t)bh * SEQ * HD;
    const float* Kg = g_K + (size_t)bh * SEQ * HD;
    const float* Vg = g_V + (size_t)bh * SEQ * HD;

    // load Q tile into fragment-native layout (prescale by 0.125)
    #pragma unroll
    for (int i = 0; i < 8; i++) {
        int idx = tid + i * 256;             // 2048 float4 units
        int r = idx >> 4, d4 = (idx & 15) * 4;
        float4 v = *(const float4*)&Qg[(size_t)(q0 + r) * HD + d4];
        int kc = d4 >> 4, t = (d4 & 15) >> 2;
        int rk = ((r >> 2) ^ kc) & 3;
        float* qd = &Qs[(((kc << 7) + r) << 4) + t];
        qd[((0^rk)<<2)] = tfbits(v.x * 0.125f);
        qd[((1^rk)<<2)] = tfbits(v.y * 0.125f);
        qd[((2^rk)<<2)] = tfbits(v.z * 0.125f);
        qd[((3^rk)<<2)] = tfbits(v.w * 0.125f);
    }

    float m0r = -1e30f, m1r = -1e30f;
    float l0r = 0.0f,  l1r = 0.0f;
    float o[8][4] = {};
    float* Pp = Ps + wid * 1024;

    const int ktiles = (q0 >> 6) + 2;
    const int maskStart = ktiles - 2;

    for (int kt = 0; kt < ktiles; kt++) {
        const int k0 = kt * 64;
        __syncthreads();                      // previous compute done reading K/V
        #pragma unroll
        for (int i = 0; i < 4; i++) {
            int idx = tid + i * 256;          // 1024 float4 units
            int c = idx >> 4, d4 = (idx & 15) * 4;
            float4 kv = *(const float4*)&Kg[(size_t)(k0 + c) * HD + d4];
            int kc = d4 >> 4, t = (d4 & 15) >> 2;
            int rkK = (((c >> 2) ^ kc)) & 3;
            float* kd = &Ks[(((kc << 6) + c) << 4) + t];
            kd[((0^rkK)<<2)] = tfbits(kv.x);
            kd[((1^rkK)<<2)] = tfbits(kv.y);
            kd[((2^rkK)<<2)] = tfbits(kv.z);
            kd[((3^rkK)<<2)] = tfbits(kv.w);
            float4 vv = *(const float4*)&Vg[(size_t)(k0 + c) * HD + d4];
            int kcv = c >> 4, tv = (c & 15) >> 2;
            int qv = ((c & 3) ^ ((d4 >> 2) & 3) ^ kcv) & 3;
            float* vd = &Vt[(((kcv << 6) + d4) << 4) + (qv << 2) + tv];
            vd[0]  = tfbits(vv.x);
            vd[16] = tfbits(vv.y);
            vd[32] = tfbits(vv.z);
            vd[48] = tfbits(vv.w);
        }
        __syncthreads();

        // S = Q K^T : warp computes 16x64
        float s[8][4] = {};
        #pragma unroll
        for (int kc = 0; kc < 4; kc++) {
            int rkQ = (rk4 ^ kc) & 3;
            int qr = (kc << 7) + wid * 16 + r4;
            float4 qlo = *(const float4*)&Qs[(qr << 4)       + (((c4 ^ rkQ)     & 3) << 2)];
            float4 qhi = *(const float4*)&Qs[((qr + 8) << 4) + (((c4 ^ rkQ ^ 2) & 3) << 2)];
            unsigned a0v[4] = {U(qlo.x), U(qhi.x), U(qlo.y), U(qhi.y)};
            unsigned a1v[4] = {U(qlo.z), U(qhi.z), U(qlo.w), U(qhi.w)};
            #pragma unroll
            for (int ni = 0; ni < 8; ni++) {
                int n = ni * 8 + r4;
                int rkB = ((2 * ni + rk4) ^ kc) & 3;
                float4 bv = *(const float4*)&Ks[(((kc << 6) + n) << 4) + (((c4 ^ rkB) & 3) << 2)];
                unsigned b0v[2] = {U(bv.x), U(bv.y)};
                unsigned b1v[2] = {U(bv.z), U(bv.w)};
                mma8(s[ni], a0v, b0v);
                mma8(s[ni], a1v, b1v);
            }
        }

        // causal mask
        if (kt >= maskStart) {
            int grow = q0 + wid * 16 + r4;
            #pragma unroll
            for (int ni = 0; ni < 8; ni++) {
                int gcol = k0 + ni * 8 + c4 * 2;
                if (gcol     > grow    ) s[ni][0] = -1e30f;
                if (gcol + 1 > grow    ) s[ni][1] = -1e30f;
                if (gcol     > grow + 8) s[ni][2] = -1e30f;
                if (gcol + 1 > grow + 8) s[ni][3] = -1e30f;
            }
        }

        // online softmax (2 rows/thread, quad reduce)
        float mx0 = -1e30f, mx1 = -1e30f;
        #pragma unroll
        for (int ni = 0; ni < 8; ni++) {
            mx0 = fmaxf(mx0, fmaxf(s[ni][0], s[ni][1]));
            mx1 = fmaxf(mx1, fmaxf(s[ni][2], s[ni][3]));
        }
        mx0 = fmaxf(mx0, __shfl_xor_sync(0xffffffffu, mx0, 1));
        mx0 = fmaxf(mx0, __shfl_xor_sync(0xffffffffu, mx0, 2));
        mx1 = fmaxf(mx1, __shfl_xor_sync(0xffffffffu, mx1, 1));
        mx1 = fmaxf(mx1, __shfl_xor_sync(0xffffffffu, mx1, 2));
        float mn0 = fmaxf(m0r, mx0), mn1 = fmaxf(m1r, mx1);
        float al0 = __expf(m0r - mn0), al1 = __expf(m1r - mn1);
        float ls0 = 0.0f, ls1 = 0.0f;
        #pragma unroll
        for (int ni = 0; ni < 8; ni++) {
            s[ni][0] = __expf(s[ni][0] - mn0);
            s[ni][1] = __expf(s[ni][1] - mn0);
            s[ni][2] = __expf(s[ni][2] - mn1);
            s[ni][3] = __expf(s[ni][3] - mn1);
            ls0 += s[ni][0] + s[ni][1];
            ls1 += s[ni][2] + s[ni][3];
        }
        ls0 += __shfl_xor_sync(0xffffffffu, ls0, 1);
        ls0 += __shfl_xor_sync(0xffffffffu, ls0, 2);
        ls1 += __shfl_xor_sync(0xffffffffu, ls1, 1);
        ls1 += __shfl_xor_sync(0xffffffffu, ls1, 2);
        l0r = l0r * al0 + ls0;  m0r = mn0;
        l1r = l1r * al1 + ls1;  m1r = mn1;

        #pragma unroll
        for (int ni = 0; ni < 8; ni++) {
            o[ni][0] *= al0; o[ni][1] *= al0;
            o[ni][2] *= al1; o[ni][3] *= al1;
        }

        // stage P (tf32) fragment-native, per-warp region
        #pragma unroll
        for (int ni = 0; ni < 8; ni++) {
            int kc  = ni >> 1;
            int c16 = ((ni & 1) << 3) + (c4 << 1);
            int tP  = c16 >> 2;
            int ql = ((c16 & 3) ^ rk4 ^ kc) & 3;
            int qh = ql ^ 2;
            float* plo = &Pp[(((kc << 4) + r4) << 4) + tP];
            float* phi = plo + (8 << 4);
            plo[(ql      << 2)] = tfbits(s[ni][0]);
            plo[((ql ^ 1) << 2)] = tfbits(s[ni][1]);
            phi[(qh      << 2)] = tfbits(s[ni][2]);
            phi[((qh ^ 1) << 2)] = tfbits(s[ni][3]);
        }
        __syncwarp();

        // O += P @ V
        #pragma unroll
        for (int kc = 0; kc < 4; kc++) {
            int rkP = (rk4 ^ kc) & 3;
            float4 plo4 = *(const float4*)&Pp[((((kc << 4) + r4    ) << 4)) + (((c4 ^ rkP)     & 3) << 2)];
            float4 phi4 = *(const float4*)&Pp[((((kc << 4) + r4 + 8) << 4)) + (((c4 ^ rkP ^ 2) & 3) << 2)];
            unsigned a0v[4] = {U(plo4.x), U(phi4.x), U(plo4.y), U(phi4.y)};
            unsigned a1v[4] = {U(plo4.z), U(phi4.z), U(plo4.w), U(phi4.w)};
            #pragma unroll
            for (int ni = 0; ni < 8; ni++) {
                int n = ni * 8 + r4;
                int rkV = ((2 * ni + rk4) ^ kc) & 3;
                float4 bv = *(const float4*)&Vt[(((kc << 6) + n) << 4) + (((c4 ^ rkV) & 3) << 2)];
                unsigned b0v[2] = {U(bv.x), U(bv.y)};
                unsigned b1v[2] = {U(bv.z), U(bv.w)};
                mma8(o[ni], a0v, b0v);
                mma8(o[ni], a1v, b1v);
            }
        }
        __syncwarp();
    }

    // epilogue: divide by l, write to g_AO (b, n, h*64+d)
    float inv0 = 1.0f / l0r, inv1 = 1.0f / l1r;
    const int b = bh >> 3, h = bh & 7;
    const int row0 = q0 + wid * 16 + r4;
    #pragma unroll
    for (int ni = 0; ni < 8; ni++) {
        int e = h * 64 + ni * 8 + c4 * 2;
        *(float2*)&g_AO[(size_t)(b * SEQ + row0    ) * EMB + e] =
            make_float2(o[ni][0] * inv0, o[ni][1] * inv0);
        *(float2*)&g_AO[(size_t)(b * SEQ + row0 + 8) * EMB + e] =
            make_float2(o[ni][2] * inv1, o[ni][3] * inv1);
    }
}

// ---------------------------------------------------------------------------

extern "C" void kernel_launch(void* const* d_in, const int* in_sizes, int n_in,
                              void* d_out, int out_size)
{
    const float* x  = (const float*)d_in[0];
    const float* WQ = (const float*)d_in[1];
    const float* WK = (const float*)d_in[2];
    const float* WV = (const float*)d_in[3];
    const float* WO = (const float*)d_in[4];
    // d_in[5] = mask (tril) — causal, applied analytically in-kernel.
    float* out = (float*)d_out;

    const int SMEM_ATTN = 24576 * (int)sizeof(float);   // 96KB
    static bool attr_set = false;
    if (!attr_set) {
        cudaFuncSetAttribute(attn_tc,
                             cudaFuncAttributeMaxDynamicSharedMemorySize, SMEM_ATTN);
        attr_set = true;
    }

    gemm_qkv<<<dim3(EMB / 128, MROWS / 128, 3), 512>>>(x, WQ, WK, WV);

    attn_tc<<<dim3(BATCH * NH, SEQ / 128), 256, SMEM_ATTN>>>();

    gemm_out<<<dim3(EMB / 128, MROWS / 128), 512>>>(WO, out);
}